// round 1
// baseline (speedup 1.0000x reference)
#include <cuda_runtime.h>
#include <cstddef>

#define H   2048
#define B   1024
#define NB  12

// Persistent state across the 23 sequential steps (device globals: no allocs).
__device__ __align__(16) float g_h[2][H];   // ping-pong hidden state
__device__ __align__(16) float g_c[H];      // cell state (in-place safe)
__device__ __align__(16) float g_x[H];      // current embedded input vector
__device__ int g_idx;                       // final argmax index

__device__ __forceinline__ float sigmoidf_(float v) {
    return 1.0f / (1.0f + expf(-v));
}

// ---------------------------------------------------------------------------
// Step 0: x = h = c = 0  =>  gates are just biases.
// ---------------------------------------------------------------------------
__global__ void k_step0(const float* __restrict__ b_ih, const float* __restrict__ b_hh) {
    int j = blockIdx.x * blockDim.x + threadIdx.x;
    if (j < H) {
        float gi = b_ih[j        ] + b_hh[j        ];
        float gg = b_ih[2 * H + j] + b_hh[2 * H + j];
        float go = b_ih[3 * H + j] + b_hh[3 * H + j];
        float c2 = sigmoidf_(gi) * tanhf(gg);      // f-gate * c0 = 0
        float h2 = sigmoidf_(go) * tanhf(c2);
        g_c[j] = c2;
        g_h[0][j] = h2;
    }
}

// ---------------------------------------------------------------------------
// One LSTM step for a single (replicated) row:
//   gates = x @ W_ih^T + h @ W_hh^T + b_ih + b_hh ; cell update.
// Grid: 512 blocks x 256 threads, 4 hidden units per block.
// Each block streams 32 weight rows (4 units x 4 gates x 2 matrices) = 256 KB.
// Pure L2/DRAM bandwidth kernel.
// ---------------------------------------------------------------------------
__global__ __launch_bounds__(256)
void k_step(const float* __restrict__ Wih, const float* __restrict__ Whh,
            const float* __restrict__ b_ih, const float* __restrict__ b_hh,
            int parity) {
    __shared__ float4 sx[H / 4];
    __shared__ float4 sh[H / 4];
    __shared__ float  wsum[8][16];
    __shared__ float  sg[16];

    const int t = threadIdx.x;
    const float* h_in = g_h[parity ^ 1];

    // Stage x and h into shared memory (vectorized).
    for (int i = t; i < H / 4; i += 256) {
        sx[i] = reinterpret_cast<const float4*>(g_x)[i];
        sh[i] = reinterpret_cast<const float4*>(h_in)[i];
    }
    __syncthreads();

    const int j0 = blockIdx.x * 4;
    const float4* Wih4 = reinterpret_cast<const float4*>(Wih);
    const float4* Whh4 = reinterpret_cast<const float4*>(Whh);

    float acc[16];
#pragma unroll
    for (int i = 0; i < 16; i++) acc[i] = 0.0f;

    // 2 iterations of k per thread; 32 LDG.128 per iteration (high MLP).
    for (int k = t; k < H / 4; k += 256) {
        float4 xv = sx[k];
        float4 hv = sh[k];
#pragma unroll
        for (int u = 0; u < 4; u++) {
            int j = j0 + u;
#pragma unroll
            for (int gg = 0; gg < 4; gg++) {
                size_t row = (size_t)(gg * H + j) * (H / 4) + k;
                float4 wi = Wih4[row];
                float4 wh = Whh4[row];
                acc[u * 4 + gg] += xv.x * wi.x + xv.y * wi.y + xv.z * wi.z + xv.w * wi.w
                                + hv.x * wh.x + hv.y * wh.y + hv.z * wh.z + hv.w * wh.w;
            }
        }
    }

    // Reduce 16 partials across the block.
    const int lane = t & 31;
    const int warp = t >> 5;
#pragma unroll
    for (int i = 0; i < 16; i++) {
        float a = acc[i];
        a += __shfl_down_sync(0xffffffffu, a, 16);
        a += __shfl_down_sync(0xffffffffu, a, 8);
        a += __shfl_down_sync(0xffffffffu, a, 4);
        a += __shfl_down_sync(0xffffffffu, a, 2);
        a += __shfl_down_sync(0xffffffffu, a, 1);
        if (lane == 0) wsum[warp][i] = a;
    }
    __syncthreads();

    if (t < 16) {
        float s = 0.0f;
#pragma unroll
        for (int w = 0; w < 8; w++) s += wsum[w][t];
        sg[t] = s;
    }
    __syncthreads();

    if (t < 4) {
        int u = t;
        int j = j0 + u;
        float gi = sg[u * 4 + 0] + b_ih[j        ] + b_hh[j        ];
        float gf = sg[u * 4 + 1] + b_ih[H     + j] + b_hh[H     + j];
        float gg = sg[u * 4 + 2] + b_ih[2 * H + j] + b_hh[2 * H + j];
        float go = sg[u * 4 + 3] + b_ih[3 * H + j] + b_hh[3 * H + j];
        float c2 = sigmoidf_(gf) * g_c[j] + sigmoidf_(gi) * tanhf(gg);
        float h2 = sigmoidf_(go) * tanhf(c2);
        g_c[j] = c2;
        g_h[parity][j] = h2;
    }
}

// ---------------------------------------------------------------------------
// Decode: logits = h @ dec^T (ncls <= 11), argmax (first-max like jnp.argmax),
// then stage the chosen embedding row into g_x for the next step.
// Single block (trivial work, but sequentially dependent).
// ---------------------------------------------------------------------------
__global__ void k_decode(const float* __restrict__ dec, int ncls,
                         const float* __restrict__ enc_next,
                         int parity, int is_final) {
    __shared__ float sl[16];
    __shared__ float wsum[8];
    __shared__ int   sidx;

    const float* h = g_h[parity];
    const int t = threadIdx.x;

    for (int c = 0; c < ncls; c++) {
        float a = 0.0f;
        for (int k = t; k < H; k += 256) a += h[k] * dec[(size_t)c * H + k];
        a += __shfl_down_sync(0xffffffffu, a, 16);
        a += __shfl_down_sync(0xffffffffu, a, 8);
        a += __shfl_down_sync(0xffffffffu, a, 4);
        a += __shfl_down_sync(0xffffffffu, a, 2);
        a += __shfl_down_sync(0xffffffffu, a, 1);
        if ((t & 31) == 0) wsum[t >> 5] = a;
        __syncthreads();
        if (t == 0) {
            float s = 0.0f;
            for (int w = 0; w < 8; w++) s += wsum[w];
            sl[c] = s;
        }
        __syncthreads();
    }

    if (t == 0) {
        int   best = 0;
        float bv   = sl[0];
        for (int c = 1; c < ncls; c++) {
            if (sl[c] > bv) { bv = sl[c]; best = c; }
        }
        sidx = best;
        if (is_final) g_idx = best;
    }
    __syncthreads();

    if (!is_final) {
        const float* e = enc_next + (size_t)sidx * H;
        for (int k = t; k < H; k += 256) g_x[k] = e[k];
    }
}

// ---------------------------------------------------------------------------
// Broadcast the single-row result to the full batch output:
//   out = [ (float)idx x 1024 , h broadcast (1024 x 2048), c broadcast ].
// ---------------------------------------------------------------------------
__global__ void k_out(float* __restrict__ out, int out_size, int parity) {
    long i = (long)blockIdx.x * blockDim.x + threadIdx.x;
    if (i >= out_size) return;
    const long HB = (long)B * H;
    float v;
    if (i < B) {
        v = (float)g_idx;
    } else if (i < B + HB) {
        v = g_h[parity][(i - B) & (H - 1)];
    } else if (i < B + 2 * HB) {
        v = g_c[(i - B - HB) & (H - 1)];
    } else {
        v = 0.0f;
    }
    __stcs(out + i, v);
}

// ---------------------------------------------------------------------------
// kernel_launch: 23 sequential steps; graph-capturable (plain launches only).
// ---------------------------------------------------------------------------
extern "C" void kernel_launch(void* const* d_in, const int* in_sizes, int n_in,
                              void* d_out, int out_size) {
    (void)in_sizes; (void)n_in;
    const float* Wih       = (const float*)d_in[1];   // (4H, H)
    const float* Whh       = (const float*)d_in[2];   // (4H, H)
    const float* b_ih      = (const float*)d_in[3];   // (4H)
    const float* b_hh      = (const float*)d_in[4];   // (4H)
    const float* enc_act   = (const float*)d_in[5];   // (11, 4, H)
    const float* enc_block = (const float*)d_in[6];   // (11, 11, H)
    const float* dec_act   = (const float*)d_in[7];   // (12, 4, H)
    const float* dec_block = (const float*)d_in[8];   // (11, 11, H)

    // Step 0 (biases only) + its decode (dec_act[0]); next table enc_act[0].
    k_step0<<<8, 256>>>(b_ih, b_hh);
    k_decode<<<1, 256>>>(dec_act, 4, enc_act, 0, 0);

    for (int s = 1; s <= 22; s++) {
        int parity = s & 1;
        k_step<<<512, 256>>>(Wih, Whh, b_ih, b_hh, parity);

        const float* dec;
        const float* enc_next;
        int ncls;
        int fin = (s == 22) ? 1 : 0;
        if (s & 1) {
            // block step, bid = (s+1)/2: decode with dec_block[bid-1] (bid valid
            // classes); next step embeds with enc_block[bid-1].
            int bid  = (s + 1) / 2;
            dec      = dec_block + (size_t)(bid - 1) * (NB - 1) * H;
            ncls     = bid;
            enc_next = enc_block + (size_t)(bid - 1) * (NB - 1) * H;
        } else {
            // activation step, bid = s/2: decode with dec_act[bid] (4 classes);
            // next step embeds with enc_act[bid].
            int bid  = s / 2;
            dec      = dec_act + (size_t)bid * 4 * H;
            ncls     = 4;
            enc_next = enc_act + (size_t)bid * 4 * H;
        }
        k_decode<<<1, 256>>>(dec, ncls, enc_next, parity, fin);
    }

    // Final state lives in g_h[0] (22 & 1 == 0).
    int nb = (out_size + 255) / 256;
    k_out<<<nb, 256>>>((float*)d_out, out_size, 0);
}

// round 2
// speedup vs baseline: 1.6825x; 1.6825x over previous
#include <cuda_runtime.h>
#include <cstddef>

#define H   2048
#define B   1024
#define NB  12
#define NROW 112          // padded candidate-row count (110 used)
#define GATES 8192        // 4*H

// ---------------------------------------------------------------------------
// Persistent device state (no allocations allowed).
// ---------------------------------------------------------------------------
__device__ __align__(16) float g_h[2][H];               // ping-pong hidden
__device__ __align__(16) float g_c[H];                  // cell state
__device__ __align__(16) float g_emb[NROW][H];          // gathered embedding rows
__device__ __align__(16) float g_pre[2][NROW][GATES];   // k-split halves of W_ih@e (+biases in half 0)
__device__ float g_part[2][12][512];                    // per-block decode partial logits

// ---------------------------------------------------------------------------
// Packed f32x2 helpers (Blackwell FFMA2 — only reachable via PTX).
// ---------------------------------------------------------------------------
__device__ __forceinline__ unsigned long long pk2(float a, float b) {
    unsigned long long p;
    asm("mov.b64 %0, {%1, %2};" : "=l"(p) : "f"(a), "f"(b));
    return p;
}
__device__ __forceinline__ void fma2(unsigned long long& d,
                                     unsigned long long a, unsigned long long b) {
    asm("fma.rn.f32x2 %0, %1, %2, %0;" : "+l"(d) : "l"(a), "l"(b));
}
__device__ __forceinline__ void unpk2(unsigned long long p, float& a, float& b) {
    asm("mov.b64 {%0, %1}, %2;" : "=f"(a), "=f"(b) : "l"(p));
}

__device__ __forceinline__ float sigmoidf_(float v) {
    return 1.0f / (1.0f + expf(-v));
}

// ---------------------------------------------------------------------------
// Gather the 110 candidate embedding rows (statically known schedule) into
// g_emb. Row r belongs to step u: ncand(u) = (u odd ? 4 : u/2), u = 1..22.
// ---------------------------------------------------------------------------
__global__ void k_gather(const float* __restrict__ enc_act,
                         const float* __restrict__ enc_block) {
    int r = blockIdx.x;
    int u = 1, base = 0, cnt = 4;
    while (u < 22 && r >= base + cnt) { base += cnt; ++u; cnt = (u & 1) ? 4 : (u >> 1); }
    const float* src;
    if (r >= base + cnt) {
        src = enc_act;                       // pad rows (110,111): duplicate row 0
    } else {
        int o = r - base;
        if (u & 1) src = enc_act   + ((size_t)((u - 1) >> 1) * 4        + o) * H;
        else       src = enc_block + ((size_t)((u >> 1) - 1) * (NB - 1) + o) * H;
    }
    const float4* s4 = (const float4*)src;
    float4*       d4 = (float4*)g_emb[r];
    for (int i = threadIdx.x; i < H / 4; i += 256) d4[i] = s4[i];
}

// ---------------------------------------------------------------------------
// Precompute GEMM: g_pre[kb][m][n] = sum_{k in half kb} Emb[m][k] * W_ih[n][k]
// (+ b_ih[n] + b_hh[n] folded into half 0).
// M=112 (2 chunks of 56), N=8192 (32 chunks of 256), K=2048 (2 halves).
// Grid = 32*2*2 = 128 blocks, 256 threads = (32 n-cols x 8 m-rows),
// thread tile = 7 m x 8 n, accumulators packed f32x2 over k-pairs.
// ---------------------------------------------------------------------------
__global__ __launch_bounds__(256)
void k_pre(const float* __restrict__ Wih,
           const float* __restrict__ b_ih, const float* __restrict__ b_hh) {
    __shared__ float Wt[32][257];   // [k][n] transposed tile
    __shared__ float Es[56][33];    // [m][k] tile

    const int bx = blockIdx.x;
    const int nb = bx & 31, mb = (bx >> 5) & 1, kb = bx >> 6;
    const int t = threadIdx.x, c = t & 31, r = t >> 5;
    const int n_base = nb * 256, m_base = mb * 56, k_base = kb * 1024;

    unsigned long long acc[7][8];
#pragma unroll
    for (int j = 0; j < 7; j++)
#pragma unroll
        for (int i = 0; i < 8; i++) acc[j][i] = 0ull;

    for (int kt = 0; kt < 1024; kt += 32) {
        const int k0 = k_base + kt;
        // cooperative load: W tile (256 n-rows x 32 k), store transposed
        {
            const float4* src = (const float4*)(Wih + (size_t)(n_base + t) * H + k0);
#pragma unroll
            for (int q = 0; q < 8; q++) {
                float4 v = src[q];
                Wt[4 * q + 0][t] = v.x; Wt[4 * q + 1][t] = v.y;
                Wt[4 * q + 2][t] = v.z; Wt[4 * q + 3][t] = v.w;
            }
        }
        // E tile (56 m-rows x 32 k)
        for (int idx = t; idx < 448; idx += 256) {
            int row = idx >> 3, q = idx & 7;
            float4 v = *(const float4*)&g_emb[m_base + row][k0 + 4 * q];
            Es[row][4 * q + 0] = v.x; Es[row][4 * q + 1] = v.y;
            Es[row][4 * q + 2] = v.z; Es[row][4 * q + 3] = v.w;
        }
        __syncthreads();

#pragma unroll
        for (int kk = 0; kk < 32; kk += 2) {
            unsigned long long w2[8], e2[7];
#pragma unroll
            for (int i = 0; i < 8; i++)
                w2[i] = pk2(Wt[kk][c + 32 * i], Wt[kk + 1][c + 32 * i]);
#pragma unroll
            for (int j = 0; j < 7; j++)
                e2[j] = pk2(Es[r * 7 + j][kk], Es[r * 7 + j][kk + 1]);
#pragma unroll
            for (int j = 0; j < 7; j++)
#pragma unroll
                for (int i = 0; i < 8; i++)
                    fma2(acc[j][i], w2[i], e2[j]);
        }
        __syncthreads();
    }

#pragma unroll
    for (int j = 0; j < 7; j++) {
        int m = m_base + r * 7 + j;
#pragma unroll
        for (int i = 0; i < 8; i++) {
            int n = n_base + c + 32 * i;
            float lo, hi;
            unpk2(acc[j][i], lo, hi);
            float v = lo + hi;
            if (kb == 0) v += b_ih[n] + b_hh[n];
            g_pre[kb][m][n] = v;
        }
    }
}

// ---------------------------------------------------------------------------
// Step 0: h=c=x=0 => gates are biases. Also emits decode-0 partial logits
// (dec_act[0], 4 classes) into g_part[1]. Grid 512 x 32 threads, 4 units/block.
// ---------------------------------------------------------------------------
__global__ void k_step0(const float* __restrict__ b_ih, const float* __restrict__ b_hh,
                        const float* __restrict__ dec0) {
    __shared__ float sh2[4];
    const int b = blockIdx.x, t = threadIdx.x;
    const int j0 = b * 4;
    if (t < 4) {
        int j = j0 + t;
        float gi = b_ih[j        ] + b_hh[j        ];
        float gg = b_ih[2 * H + j] + b_hh[2 * H + j];
        float go = b_ih[3 * H + j] + b_hh[3 * H + j];
        float c2 = sigmoidf_(gi) * tanhf(gg);
        float h2 = sigmoidf_(go) * tanhf(c2);
        g_c[j] = c2;
        g_h[0][j] = h2;
        sh2[t] = h2;
    }
    __syncwarp();
    if (t < 4) {  // class t partial logit over this block's 4 units
        float s = 0.0f;
#pragma unroll
        for (int u = 0; u < 4; u++) s += sh2[u] * dec0[(size_t)t * H + j0 + u];
        g_part[1][t][b] = s;
    }
}

// ---------------------------------------------------------------------------
// One fused step (s = 1..22):
//   prologue: reduce previous step's partial logits (deterministic order),
//             argmax -> select precomputed gate row.
//   main:     gates = pre[sel] + W_hh @ h   (W_hh stays L2-resident: 64 MB)
//   epilogue: cell update; emit this step's decode partial logits.
// Grid 512 x 256, 4 hidden units per block (16 W_hh rows = 128 KB streamed).
// ---------------------------------------------------------------------------
__global__ __launch_bounds__(256)
void k_step(const float* __restrict__ Whh, const float* __restrict__ dec,
            int parity, int cand_base, int ncand, int ncls, int pr, int pw) {
    __shared__ float4 sh4[H / 4];
    __shared__ float  wsum[8][16];
    __shared__ float  sg[16];
    __shared__ float  slog[12];
    __shared__ int    ssel;
    __shared__ float  sh2[4];

    const int t = threadIdx.x;
    const int lane = t & 31, warp = t >> 5;

    // stage h (issue early)
    const float4* h4 = (const float4*)g_h[parity ^ 1];
    for (int i = t; i < H / 4; i += 256) sh4[i] = h4[i];

    // prologue: per-class sums of 512 block-partials, then argmax (first-max)
    for (int cls = warp; cls < ncand; cls += 8) {
        const float* p = g_part[pr][cls];
        float a = 0.0f;
#pragma unroll
        for (int i = 0; i < 16; i++) a += p[lane + 32 * i];
        a += __shfl_down_sync(0xffffffffu, a, 16);
        a += __shfl_down_sync(0xffffffffu, a, 8);
        a += __shfl_down_sync(0xffffffffu, a, 4);
        a += __shfl_down_sync(0xffffffffu, a, 2);
        a += __shfl_down_sync(0xffffffffu, a, 1);
        if (lane == 0) slog[cls] = a;
    }
    __syncthreads();
    if (t == 0) {
        int best = 0; float bv = slog[0];
        for (int cc = 1; cc < ncand; cc++)
            if (slog[cc] > bv) { bv = slog[cc]; best = cc; }
        ssel = cand_base + best;
    }
    __syncthreads();

    // main: h @ W_hh^T for this block's 16 rows
    const int j0 = blockIdx.x * 4;
    const float4* W4 = (const float4*)Whh;
    float acc[16];
#pragma unroll
    for (int i = 0; i < 16; i++) acc[i] = 0.0f;

    for (int k = t; k < H / 4; k += 256) {
        float4 hv = sh4[k];
#pragma unroll
        for (int u = 0; u < 4; u++) {
#pragma unroll
            for (int gg = 0; gg < 4; gg++) {
                float4 w = W4[(size_t)(gg * H + j0 + u) * (H / 4) + k];
                acc[u * 4 + gg] += hv.x * w.x + hv.y * w.y + hv.z * w.z + hv.w * w.w;
            }
        }
    }

#pragma unroll
    for (int i = 0; i < 16; i++) {
        float a = acc[i];
        a += __shfl_down_sync(0xffffffffu, a, 16);
        a += __shfl_down_sync(0xffffffffu, a, 8);
        a += __shfl_down_sync(0xffffffffu, a, 4);
        a += __shfl_down_sync(0xffffffffu, a, 2);
        a += __shfl_down_sync(0xffffffffu, a, 1);
        if (lane == 0) wsum[warp][i] = a;
    }
    __syncthreads();
    if (t < 16) {
        float s = 0.0f;
#pragma unroll
        for (int w = 0; w < 8; w++) s += wsum[w][t];
        sg[t] = s;
    }
    __syncthreads();

    if (t < 4) {
        const int row = ssel;
        const float* p0 = g_pre[0][row];
        const float* p1 = g_pre[1][row];
        int j = j0 + t;
        float gi = sg[t * 4 + 0] + p0[j        ] + p1[j        ];
        float gf = sg[t * 4 + 1] + p0[H     + j] + p1[H     + j];
        float gg = sg[t * 4 + 2] + p0[2 * H + j] + p1[2 * H + j];
        float go = sg[t * 4 + 3] + p0[3 * H + j] + p1[3 * H + j];
        float c2 = sigmoidf_(gf) * g_c[j] + sigmoidf_(gi) * tanhf(gg);
        float h2 = sigmoidf_(go) * tanhf(c2);
        g_c[j] = c2;
        g_h[parity][j] = h2;
        sh2[t] = h2;
    }
    __syncthreads();

    // epilogue decode partials for this step
    if (t < ncls) {
        float s = 0.0f;
#pragma unroll
        for (int u = 0; u < 4; u++) s += sh2[u] * dec[(size_t)t * H + j0 + u];
        g_part[pw][t][blockIdx.x] = s;
    }
}

// ---------------------------------------------------------------------------
// Output: final argmax (dec_act[11] partials in g_part[1], 4 classes) + the
// broadcast of (idx, h, c) to the batch. Only blocks 0..3 need the argmax.
// ---------------------------------------------------------------------------
__global__ void k_out(float* __restrict__ out, int out_size) {
    __shared__ float swsum[8];
    __shared__ int   sidx;
    const int t = threadIdx.x;
    long i = (long)blockIdx.x * 256 + t;

    if (blockIdx.x < 4) {
        const int warp = t >> 5, lane = t & 31;
        const int cls = warp & 3, half = warp >> 2;
        float a = 0.0f;
#pragma unroll
        for (int q = 0; q < 8; q++) a += g_part[1][cls][lane + 32 * (half * 8 + q)];
        a += __shfl_down_sync(0xffffffffu, a, 16);
        a += __shfl_down_sync(0xffffffffu, a, 8);
        a += __shfl_down_sync(0xffffffffu, a, 4);
        a += __shfl_down_sync(0xffffffffu, a, 2);
        a += __shfl_down_sync(0xffffffffu, a, 1);
        if (lane == 0) swsum[warp] = a;
        __syncthreads();
        if (t == 0) {
            int best = 0; float bv = swsum[0] + swsum[4];
            for (int cc = 1; cc < 4; cc++) {
                float v = swsum[cc] + swsum[cc + 4];
                if (v > bv) { bv = v; best = cc; }
            }
            sidx = best;
        }
        __syncthreads();
    }

    if (i >= out_size) return;
    const long HB = (long)B * H;
    float v;
    if (i < B) {
        v = (float)sidx;
    } else if (i < B + HB) {
        v = g_h[0][(i - B) & (H - 1)];
    } else if (i < B + 2 * HB) {
        v = g_c[(i - B - HB) & (H - 1)];
    } else {
        v = 0.0f;
    }
    __stcs(out + i, v);
}

// ---------------------------------------------------------------------------
// kernel_launch: gather + precompute GEMM + 23 fused steps + output.
// ---------------------------------------------------------------------------
extern "C" void kernel_launch(void* const* d_in, const int* in_sizes, int n_in,
                              void* d_out, int out_size) {
    (void)in_sizes; (void)n_in;
    const float* Wih       = (const float*)d_in[1];
    const float* Whh       = (const float*)d_in[2];
    const float* b_ih      = (const float*)d_in[3];
    const float* b_hh      = (const float*)d_in[4];
    const float* enc_act   = (const float*)d_in[5];
    const float* enc_block = (const float*)d_in[6];
    const float* dec_act   = (const float*)d_in[7];
    const float* dec_block = (const float*)d_in[8];

    k_gather<<<NROW, 256>>>(enc_act, enc_block);
    k_pre<<<128, 256>>>(Wih, b_ih, b_hh);
    k_step0<<<512, 32>>>(b_ih, b_hh, dec_act);

    int base = 0, cnt = 4;  // candidates for step 1
    for (int s = 1; s <= 22; s++) {
        const float* dec;
        int ncls;
        if (s & 1) { // block decode
            int bid = (s + 1) / 2;
            dec  = dec_block + (size_t)(bid - 1) * (NB - 1) * H;
            ncls = bid;
        } else {     // activation decode
            dec  = dec_act + (size_t)(s / 2) * 4 * H;
            ncls = 4;
        }
        k_step<<<512, 256>>>(Whh, dec, s & 1, base, cnt, ncls, s & 1, (s + 1) & 1);
        base += cnt;
        cnt = ((s + 1) & 1) ? 4 : ((s + 1) >> 1);  // ncand(s+1)
    }

    int nb = (out_size + 255) / 256;
    k_out<<<nb, 256>>>((float*)d_out, out_size);
}

// round 3
// speedup vs baseline: 1.7274x; 1.0267x over previous
#include <cuda_runtime.h>
#include <cstddef>

#define H     2048
#define B     1024
#define NB    12
#define NROW  112
#define GATES 8192
#define NBLK  512
#define KC    704            // k-prefix of each W_hh row cached in smem
#define KC4   (KC / 4)       // 176 float4
#define DSMEM (16 * KC * 4 + (H / 4) * 16)   // 45056 + 8192 = 53248 B

// ---------------------------------------------------------------------------
// Persistent device state (no allocations).
// ---------------------------------------------------------------------------
__device__ __align__(16) float g_h[2][H];
__device__ __align__(16) float g_c[H];
__device__ __align__(16) float g_emb[NROW][H];
__device__ __align__(16) float g_pre[4][NROW][GATES];   // k-quarter partials (+biases in q0)
__device__ float g_part[2][12][NBLK];                   // decode partial logits
__device__ unsigned g_cnt[32 * 8];                      // barrier counters, 32B-padded

__device__ __forceinline__ float sigmoidf_(float v) { return 1.0f / (1.0f + expf(-v)); }

__device__ __forceinline__ unsigned long long pk2(float a, float b) {
    unsigned long long p;
    asm("mov.b64 %0, {%1, %2};" : "=l"(p) : "f"(a), "f"(b));
    return p;
}
__device__ __forceinline__ void fma2(unsigned long long& d,
                                     unsigned long long a, unsigned long long b) {
    asm("fma.rn.f32x2 %0, %1, %2, %0;" : "+l"(d) : "l"(a), "l"(b));
}
__device__ __forceinline__ void unpk2(unsigned long long p, float& a, float& b) {
    asm("mov.b64 {%0, %1}, %2;" : "=f"(a), "=f"(b) : "l"(p));
}

// ---------------------------------------------------------------------------
// Grid barrier: 32 padded counters, 16 arrivals each; warp 0 polls all 32.
// ---------------------------------------------------------------------------
__device__ __forceinline__ void gsync(unsigned target16) {
    __syncthreads();
    if (threadIdx.x == 0) {
        __threadfence();
        atomicAdd(&g_cnt[(blockIdx.x & 31) * 8], 1u);
    }
    if (threadIdx.x < 32) {
        while (*(volatile unsigned*)&g_cnt[threadIdx.x * 8] < target16) __nanosleep(60);
    }
    __syncthreads();
}

__global__ void k_init() {
    if (threadIdx.x < 32 * 8) g_cnt[threadIdx.x] = 0u;
}

// ---------------------------------------------------------------------------
// Gather 110 candidate embedding rows (static schedule) into g_emb.
// ---------------------------------------------------------------------------
__global__ void k_gather(const float* __restrict__ enc_act,
                         const float* __restrict__ enc_block) {
    int r = blockIdx.x;
    int u = 1, base = 0, cnt = 4;
    while (u < 22 && r >= base + cnt) { base += cnt; ++u; cnt = (u & 1) ? 4 : (u >> 1); }
    const float* src;
    if (r >= base + cnt) {
        src = enc_act;   // pad rows
    } else {
        int o = r - base;
        if (u & 1) src = enc_act   + ((size_t)((u - 1) >> 1) * 4        + o) * H;
        else       src = enc_block + ((size_t)((u >> 1) - 1) * (NB - 1) + o) * H;
    }
    const float4* s4 = (const float4*)src;
    float4*       d4 = (float4*)g_emb[r];
    for (int i = threadIdx.x; i < H / 4; i += 256) d4[i] = s4[i];
}

// ---------------------------------------------------------------------------
// Precompute GEMM: g_pre[kb][m][n] = sum_{k in quarter kb} Emb[m][k]*W_ih[n][k]
// (+biases in kb 0). Grid 256 = 32 nb x 2 mb x 4 kb, 256 thr (32c x 8r),
// thread tile 7m x 8n, packed f32x2 accumulators.
// ---------------------------------------------------------------------------
__global__ __launch_bounds__(256)
void k_pre(const float* __restrict__ Wih,
           const float* __restrict__ b_ih, const float* __restrict__ b_hh) {
    __shared__ float Wt[32][257];
    __shared__ float Es[56][33];

    const int bx = blockIdx.x;
    const int nb = bx & 31, mb = (bx >> 5) & 1, kb = bx >> 6;
    const int t = threadIdx.x, c = t & 31, r = t >> 5;
    const int n_base = nb * 256, m_base = mb * 56, k_base = kb * 512;

    unsigned long long acc[7][8];
#pragma unroll
    for (int j = 0; j < 7; j++)
#pragma unroll
        for (int i = 0; i < 8; i++) acc[j][i] = 0ull;

    for (int kt = 0; kt < 512; kt += 32) {
        const int k0 = k_base + kt;
        {
            const float4* src = (const float4*)(Wih + (size_t)(n_base + t) * H + k0);
#pragma unroll
            for (int q = 0; q < 8; q++) {
                float4 v = src[q];
                Wt[4 * q + 0][t] = v.x; Wt[4 * q + 1][t] = v.y;
                Wt[4 * q + 2][t] = v.z; Wt[4 * q + 3][t] = v.w;
            }
        }
        for (int idx = t; idx < 448; idx += 256) {
            int row = idx >> 3, q = idx & 7;
            float4 v = *(const float4*)&g_emb[m_base + row][k0 + 4 * q];
            Es[row][4 * q + 0] = v.x; Es[row][4 * q + 1] = v.y;
            Es[row][4 * q + 2] = v.z; Es[row][4 * q + 3] = v.w;
        }
        __syncthreads();

#pragma unroll
        for (int kk = 0; kk < 32; kk += 2) {
            unsigned long long w2[8], e2[7];
#pragma unroll
            for (int i = 0; i < 8; i++)
                w2[i] = pk2(Wt[kk][c + 32 * i], Wt[kk + 1][c + 32 * i]);
#pragma unroll
            for (int j = 0; j < 7; j++)
                e2[j] = pk2(Es[r * 7 + j][kk], Es[r * 7 + j][kk + 1]);
#pragma unroll
            for (int j = 0; j < 7; j++)
#pragma unroll
                for (int i = 0; i < 8; i++)
                    fma2(acc[j][i], w2[i], e2[j]);
        }
        __syncthreads();
    }

#pragma unroll
    for (int j = 0; j < 7; j++) {
        int m = m_base + r * 7 + j;
#pragma unroll
        for (int i = 0; i < 8; i++) {
            int n = n_base + c + 32 * i;
            float lo, hi;
            unpk2(acc[j][i], lo, hi);
            float v = lo + hi;
            if (kb == 0) v += b_ih[n] + b_hh[n];
            g_pre[kb][m][n] = v;
        }
    }
}

// ---------------------------------------------------------------------------
// Persistent kernel: step0 + 22 fused LSTM steps + output broadcast.
// 512 blocks x 256 threads, 4 blocks/SM co-resident (deadlock-safe).
// Block b owns hidden units j0=4b..4b+3 (16 W_hh rows); k-prefix of those
// rows lives in smem for all 22 steps, remainder streams from L2.
// ---------------------------------------------------------------------------
__global__ __launch_bounds__(256, 4)
void k_persist(const float* __restrict__ Whh,
               const float* __restrict__ b_ih, const float* __restrict__ b_hh,
               const float* __restrict__ dec_act, const float* __restrict__ dec_block,
               float* __restrict__ out, int out_size) {
    extern __shared__ float dyn[];
    float*  wc  = dyn;                                  // [16][KC]
    float4* sh4 = (float4*)(dyn + 16 * KC);             // [H/4]

    __shared__ float wsum[8][16];
    __shared__ float sg[16];
    __shared__ float slog[12];
    __shared__ float sh2[4];
    __shared__ float scell[4];
    __shared__ int   ssel;

    const int bid = blockIdx.x, t = threadIdx.x;
    const int lane = t & 31, warp = t >> 5;
    const int j0 = bid * 4;
    const float4* W4 = (const float4*)Whh;

    // ---- load this block's W_hh k-prefix into smem (once) ----
    for (int idx = t; idx < 16 * KC4; idx += 256) {
        int r = idx / KC4, q = idx - r * KC4;
        size_t grow = (size_t)((r & 3) * H + j0 + (r >> 2));
        *(float4*)&wc[r * KC + 4 * q] = W4[grow * (H / 4) + q];
    }

    // ---- step 0: h=c=x=0 -> gates are biases; emit decode-0 partials ----
    if (t < 4) {
        int j = j0 + t;
        float gi = b_ih[j        ] + b_hh[j        ];
        float gg = b_ih[2 * H + j] + b_hh[2 * H + j];
        float go = b_ih[3 * H + j] + b_hh[3 * H + j];
        float c2 = sigmoidf_(gi) * tanhf(gg);
        float h2 = sigmoidf_(go) * tanhf(c2);
        scell[t] = c2;
        __stcg(&g_h[0][j], h2);
        sh2[t] = h2;
    }
    __syncthreads();
    if (t < 4) {
        float s = 0.0f;
#pragma unroll
        for (int u = 0; u < 4; u++) s += sh2[u] * dec_act[(size_t)t * H + j0 + u];
        __stcg(&g_part[1][t][bid], s);
    }

    unsigned phase = 1;
    gsync(phase * 16);

    // ---- 22 fused steps ----
    int cand_base = 0, ncand = 4;
    for (int s = 1; s <= 22; s++) {
        const int parity = s & 1, pr = s & 1, pw = (s + 1) & 1;

        // stage h from L2 (coherent) into smem
        const float4* h4 = (const float4*)g_h[parity ^ 1];
        for (int i = t; i < H / 4; i += 256) sh4[i] = __ldcg(&h4[i]);

        // prologue: reduce previous decode partials, argmax -> candidate row
        for (int cls = warp; cls < ncand; cls += 8) {
            const float* p = g_part[pr][cls];
            float a = 0.0f;
#pragma unroll
            for (int i = 0; i < 16; i++) a += __ldcg(&p[lane + 32 * i]);
            a += __shfl_down_sync(0xffffffffu, a, 16);
            a += __shfl_down_sync(0xffffffffu, a, 8);
            a += __shfl_down_sync(0xffffffffu, a, 4);
            a += __shfl_down_sync(0xffffffffu, a, 2);
            a += __shfl_down_sync(0xffffffffu, a, 1);
            if (lane == 0) slog[cls] = a;
        }
        __syncthreads();
        if (t == 0) {
            int best = 0; float bv = slog[0];
            for (int cc = 1; cc < ncand; cc++)
                if (slog[cc] > bv) { bv = slog[cc]; best = cc; }
            ssel = cand_base + best;
        }
        __syncthreads();

        // main GEMV: 16 rows; k4<KC4 from smem, rest streamed (L2-resident)
        float acc[16];
#pragma unroll
        for (int i = 0; i < 16; i++) acc[i] = 0.0f;

        for (int k4 = t; k4 < H / 4; k4 += 256) {
            float4 hv = sh4[k4];
            if (k4 < KC4) {
#pragma unroll
                for (int r = 0; r < 16; r++) {
                    float4 w = *(const float4*)&wc[r * KC + 4 * k4];
                    acc[r] += hv.x * w.x + hv.y * w.y + hv.z * w.z + hv.w * w.w;
                }
            } else {
#pragma unroll
                for (int u = 0; u < 4; u++) {
#pragma unroll
                    for (int gg = 0; gg < 4; gg++) {
                        float4 w = W4[(size_t)(gg * H + j0 + u) * (H / 4) + k4];
                        acc[u * 4 + gg] += hv.x * w.x + hv.y * w.y + hv.z * w.z + hv.w * w.w;
                    }
                }
            }
        }

#pragma unroll
        for (int i = 0; i < 16; i++) {
            float a = acc[i];
            a += __shfl_down_sync(0xffffffffu, a, 16);
            a += __shfl_down_sync(0xffffffffu, a, 8);
            a += __shfl_down_sync(0xffffffffu, a, 4);
            a += __shfl_down_sync(0xffffffffu, a, 2);
            a += __shfl_down_sync(0xffffffffu, a, 1);
            if (lane == 0) wsum[warp][i] = a;
        }
        __syncthreads();
        if (t < 16) {
            float sm = 0.0f;
#pragma unroll
            for (int w = 0; w < 8; w++) sm += wsum[w][t];
            sg[t] = sm;
        }
        __syncthreads();

        if (t < 4) {
            const int row = ssel;
            const float* p0 = g_pre[0][row];
            const float* p1 = g_pre[1][row];
            const float* p2 = g_pre[2][row];
            const float* p3 = g_pre[3][row];
            int j = j0 + t;
            float gi = sg[t * 4 + 0] + p0[j        ] + p1[j        ] + p2[j        ] + p3[j        ];
            float gf = sg[t * 4 + 1] + p0[H     + j] + p1[H     + j] + p2[H     + j] + p3[H     + j];
            float gg = sg[t * 4 + 2] + p0[2 * H + j] + p1[2 * H + j] + p2[2 * H + j] + p3[2 * H + j];
            float go = sg[t * 4 + 3] + p0[3 * H + j] + p1[3 * H + j] + p2[3 * H + j] + p3[3 * H + j];
            float c2 = sigmoidf_(gf) * scell[t] + sigmoidf_(gi) * tanhf(gg);
            float h2 = sigmoidf_(go) * tanhf(c2);
            scell[t] = c2;
            __stcg(&g_h[parity][j], h2);
            sh2[t] = h2;
            if (s == 22) __stcg(&g_c[j], c2);
        }
        __syncthreads();

        // epilogue: this step's decode partials
        const float* dec;
        int ncls;
        if (s & 1) {
            int bid_ = (s + 1) / 2;
            dec  = dec_block + (size_t)(bid_ - 1) * (NB - 1) * H;
            ncls = bid_;
        } else {
            dec  = dec_act + (size_t)(s / 2) * 4 * H;
            ncls = 4;
        }
        if (t < ncls) {
            float sm = 0.0f;
#pragma unroll
            for (int u = 0; u < 4; u++) sm += sh2[u] * dec[(size_t)t * H + j0 + u];
            __stcg(&g_part[pw][t][bid], sm);
        }

        cand_base += ncand;
        ncand = ((s + 1) & 1) ? 4 : ((s + 1) >> 1);

        ++phase;
        gsync(phase * 16);
    }

    // ---- final argmax (dec partials of step 22 in g_part[1], 4 classes) ----
    for (int cls = warp; cls < 4; cls += 8) {
        const float* p = g_part[1][cls];
        float a = 0.0f;
#pragma unroll
        for (int i = 0; i < 16; i++) a += __ldcg(&p[lane + 32 * i]);
        a += __shfl_down_sync(0xffffffffu, a, 16);
        a += __shfl_down_sync(0xffffffffu, a, 8);
        a += __shfl_down_sync(0xffffffffu, a, 4);
        a += __shfl_down_sync(0xffffffffu, a, 2);
        a += __shfl_down_sync(0xffffffffu, a, 1);
        if (lane == 0) slog[cls] = a;
    }
    __syncthreads();
    if (t == 0) {
        int best = 0; float bv = slog[0];
        for (int cc = 1; cc < 4; cc++)
            if (slog[cc] > bv) { bv = slog[cc]; best = cc; }
        ssel = best;
    }
    __syncthreads();

    // ---- output broadcast: [idx x1024 | h x(1024x2048) | c x(1024x2048)] ----
    const float fidx = (float)ssel;
    const long HB = (long)B * H;
    for (long i = (long)bid * 256 + t; i < out_size; i += (long)NBLK * 256) {
        float v;
        if (i < B)               v = fidx;
        else if (i < B + HB)     v = __ldcg(&g_h[0][(i - B) & (H - 1)]);
        else if (i < B + 2 * HB) v = __ldcg(&g_c[(i - B - HB) & (H - 1)]);
        else                     v = 0.0f;
        __stcs(out + i, v);
    }
}

// ---------------------------------------------------------------------------
extern "C" void kernel_launch(void* const* d_in, const int* in_sizes, int n_in,
                              void* d_out, int out_size) {
    (void)in_sizes; (void)n_in;
    const float* Wih       = (const float*)d_in[1];
    const float* Whh       = (const float*)d_in[2];
    const float* b_ih      = (const float*)d_in[3];
    const float* b_hh      = (const float*)d_in[4];
    const float* enc_act   = (const float*)d_in[5];
    const float* enc_block = (const float*)d_in[6];
    const float* dec_act   = (const float*)d_in[7];
    const float* dec_block = (const float*)d_in[8];

    static int attr_done = 0;
    if (!attr_done) {
        cudaFuncSetAttribute(k_persist, cudaFuncAttributeMaxDynamicSharedMemorySize, DSMEM);
        attr_done = 1;
    }

    k_init<<<1, 256>>>();
    k_gather<<<NROW, 256>>>(enc_act, enc_block);
    k_pre<<<256, 256>>>(Wih, b_ih, b_hh);
    k_persist<<<NBLK, 256, DSMEM>>>(Whh, b_ih, b_hh, dec_act, dec_block,
                                    (float*)d_out, out_size);
}

// round 5
// speedup vs baseline: 2.5341x; 1.4670x over previous
#include <cuda_runtime.h>
#include <cstddef>

#define H     2048
#define B     1024
#define NB    12
#define NROW  112
#define GATES 8192
#define NBLK  128                 // persistent blocks (1/SM, co-resident)
#define KC4   192                 // float4 k-prefix of each W_hh row in smem
#define KC    (KC4 * 4)           // 768 floats
#define P_DSMEM (64 * KC4 * 16)   // 196608 B: 64 rows x 192 float4

// k_pre dynamic smem: Wt2 [256][17] float2 + Es2 [56][17] float2
#define PRE_W_F2   (256 * 17)
#define PRE_E_F2   (56 * 17)
#define PRE_DSMEM  ((PRE_W_F2 + PRE_E_F2) * 8)   // 42432 B

// ---------------------------------------------------------------------------
__device__ __align__(16) float g_h[2][H];
__device__ __align__(16) float g_c[H];
__device__ __align__(16) float g_emb[NROW][H];
__device__ __align__(16) float g_pre[4][NROW][GATES];
__device__ float g_part[2][12][NBLK];
__device__ unsigned g_cnt[32 * 8];

__device__ __forceinline__ float sigmoidf_(float v) { return 1.0f / (1.0f + expf(-v)); }

__device__ __forceinline__ unsigned long long pk2(float a, float b) {
    unsigned long long p;
    asm("mov.b64 %0, {%1, %2};" : "=l"(p) : "f"(a), "f"(b));
    return p;
}
__device__ __forceinline__ void fma2(unsigned long long& d,
                                     unsigned long long a, unsigned long long b) {
    asm("fma.rn.f32x2 %0, %1, %2, %0;" : "+l"(d) : "l"(a), "l"(b));
}
__device__ __forceinline__ void unpk2(unsigned long long p, float& a, float& b) {
    asm("mov.b64 {%0, %1}, %2;" : "=f"(a), "=f"(b) : "l"(p));
}

// ---------------------------------------------------------------------------
// Grid barrier for 128 blocks: 32 padded counters, 4 arrivals each.
// ---------------------------------------------------------------------------
__device__ __forceinline__ void gsync(unsigned target4) {
    __syncthreads();
    if (threadIdx.x == 0) {
        __threadfence();
        atomicAdd(&g_cnt[(blockIdx.x & 31) * 8], 1u);
    }
    if (threadIdx.x < 32) {
        while (*(volatile unsigned*)&g_cnt[threadIdx.x * 8] < target4) __nanosleep(40);
    }
    __syncthreads();
}

__global__ void k_init() {
    if (threadIdx.x < 32 * 8) g_cnt[threadIdx.x] = 0u;
}

// ---------------------------------------------------------------------------
// Gather 110 candidate embedding rows (static schedule) into g_emb.
// ---------------------------------------------------------------------------
__global__ void k_gather(const float* __restrict__ enc_act,
                         const float* __restrict__ enc_block) {
    int r = blockIdx.x;
    int u = 1, base = 0, cnt = 4;
    while (u < 22 && r >= base + cnt) { base += cnt; ++u; cnt = (u & 1) ? 4 : (u >> 1); }
    const float* src;
    if (r >= base + cnt) {
        src = enc_act;
    } else {
        int o = r - base;
        if (u & 1) src = enc_act   + ((size_t)((u - 1) >> 1) * 4        + o) * H;
        else       src = enc_block + ((size_t)((u >> 1) - 1) * (NB - 1) + o) * H;
    }
    const float4* s4 = (const float4*)src;
    float4*       d4 = (float4*)g_emb[r];
    for (int i = threadIdx.x; i < H / 4; i += 256) d4[i] = s4[i];
}

// ---------------------------------------------------------------------------
// Precompute GEMM (packed f32x2): 128 blocks x 2 tiles (perfect 1-wave).
// Tile = (nb,mb,kb) of 256n x 56m x 512k. LDS.64-friendly float2 layouts,
// register-staged prefetch of next k-slab.
// ---------------------------------------------------------------------------
__global__ __launch_bounds__(256)
void k_pre(const float* __restrict__ Wih,
           const float* __restrict__ b_ih, const float* __restrict__ b_hh) {
    extern __shared__ float2 dynp[];
    float2* Wt2 = dynp;               // [256][17] : [n_local][kk2], pitch 17
    float2* Es2 = dynp + PRE_W_F2;    // [56][17]

    const int t = threadIdx.x, c = t & 31, r = t >> 5;

    for (int tile = blockIdx.x; tile < 256; tile += 128) {
        const int nb = tile & 31, mb = (tile >> 5) & 1, kb = tile >> 6;
        const int n_base = nb * 256, m_base = mb * 56, k_base = kb * 512;

        unsigned long long acc[7][8];
#pragma unroll
        for (int j = 0; j < 7; j++)
#pragma unroll
            for (int i = 0; i < 8; i++) acc[j][i] = 0ull;

        // register staging for next slab
        float4 wst[8];
        float4 est[2];

        // preload slab kt=0
        {
            const float4* wsrc = (const float4*)(Wih + (size_t)(n_base + t) * H + k_base);
#pragma unroll
            for (int q = 0; q < 8; q++) wst[q] = __ldcg(&wsrc[q]);
#pragma unroll
            for (int x = 0; x < 2; x++) {
                int idx = t + 256 * x;
                if (idx < 448) {
                    int row = idx >> 3, q = idx & 7;
                    est[x] = *(const float4*)&g_emb[m_base + row][k_base + 4 * q];
                }
            }
        }

        for (int kt = 0; kt < 512; kt += 32) {
            // commit staged regs to smem
            {
                float2* wd = &Wt2[t * 17];
#pragma unroll
                for (int q = 0; q < 8; q++) {
                    wd[2 * q + 0] = make_float2(wst[q].x, wst[q].y);
                    wd[2 * q + 1] = make_float2(wst[q].z, wst[q].w);
                }
#pragma unroll
                for (int x = 0; x < 2; x++) {
                    int idx = t + 256 * x;
                    if (idx < 448) {
                        int row = idx >> 3, q = idx & 7;
                        Es2[row * 17 + 2 * q + 0] = make_float2(est[x].x, est[x].y);
                        Es2[row * 17 + 2 * q + 1] = make_float2(est[x].z, est[x].w);
                    }
                }
            }
            __syncthreads();

            // issue loads for next slab (overlap with compute below)
            if (kt + 32 < 512) {
                const int k0 = k_base + kt + 32;
                const float4* wsrc = (const float4*)(Wih + (size_t)(n_base + t) * H + k0);
#pragma unroll
                for (int q = 0; q < 8; q++) wst[q] = __ldcg(&wsrc[q]);
#pragma unroll
                for (int x = 0; x < 2; x++) {
                    int idx = t + 256 * x;
                    if (idx < 448) {
                        int row = idx >> 3, q = idx & 7;
                        est[x] = *(const float4*)&g_emb[m_base + row][k0 + 4 * q];
                    }
                }
            }

            // compute current slab
#pragma unroll
            for (int kk2 = 0; kk2 < 16; kk2++) {
                unsigned long long w2[8], e2[7];
#pragma unroll
                for (int i = 0; i < 8; i++)
                    w2[i] = *(const unsigned long long*)&Wt2[(c + 32 * i) * 17 + kk2];
#pragma unroll
                for (int j = 0; j < 7; j++)
                    e2[j] = *(const unsigned long long*)&Es2[(r * 7 + j) * 17 + kk2];
#pragma unroll
                for (int j = 0; j < 7; j++)
#pragma unroll
                    for (int i = 0; i < 8; i++)
                        fma2(acc[j][i], w2[i], e2[j]);
            }
            __syncthreads();
        }

#pragma unroll
        for (int j = 0; j < 7; j++) {
            int m = m_base + r * 7 + j;
#pragma unroll
            for (int i = 0; i < 8; i++) {
                int n = n_base + c + 32 * i;
                float lo, hi;
                unpk2(acc[j][i], lo, hi);
                float v = lo + hi;
                if (kb == 0) v += b_ih[n] + b_hh[n];
                g_pre[kb][m][n] = v;
            }
        }
        __syncthreads();
    }
}

// ---------------------------------------------------------------------------
// Persistent kernel: 128 blocks x 1024 threads, 16 hidden units per block
// (64 W_hh rows). Row R = g*16 + u. Thread t: rg = t>>8 (gate), kq = t&255.
// ---------------------------------------------------------------------------
__global__ __launch_bounds__(1024, 1)
void k_persist(const float* __restrict__ Whh,
               const float* __restrict__ b_ih, const float* __restrict__ b_hh,
               const float* __restrict__ dec_act, const float* __restrict__ dec_block,
               float* __restrict__ out, int out_size) {
    extern __shared__ float dyn[];
    float4* wc4 = (float4*)dyn;                 // [64][KC4]

    __shared__ float wsum[4][8][16];
    __shared__ float sg[64];
    __shared__ float spre[256];
    __shared__ float slog[12];
    __shared__ float sunit[16];
    __shared__ float scell[16];
    __shared__ int   ssel;

    const int bid = blockIdx.x, t = threadIdx.x;
    const int lane = t & 31, warp = t >> 5;
    const int rg = t >> 8, kq = t & 255, wig = (t >> 5) & 7;  // warp-in-gate
    const int j0 = bid * 16;
    const float4* W4 = (const float4*)Whh;

    // ---- one-time: load W_hh k-prefix (64 rows x KC4 float4) into smem ----
    for (int idx = t; idx < 64 * KC4; idx += 1024) {
        int R = idx / KC4, q = idx - R * KC4;
        size_t grow = (size_t)((R >> 4) * H + j0 + (R & 15));
        wc4[R * KC4 + q] = __ldcg(&W4[grow * (H / 4) + q]);
    }

    // ---- step 0: gates = biases; decode-0 partials into g_part[1] ----
    if (t < 16) {
        int j = j0 + t;
        float gi = b_ih[j        ] + b_hh[j        ];
        float gg = b_ih[2 * H + j] + b_hh[2 * H + j];
        float go = b_ih[3 * H + j] + b_hh[3 * H + j];
        float c2 = sigmoidf_(gi) * tanhf(gg);
        float h2 = sigmoidf_(go) * tanhf(c2);
        scell[t] = c2;
        sunit[t] = h2;
        __stcg(&g_h[0][j], h2);
    }
    __syncthreads();
    if (warp < 4) {
        float v = (lane < 16) ? sunit[lane] * __ldg(&dec_act[(size_t)warp * H + j0 + lane]) : 0.0f;
        v += __shfl_down_sync(0xffffffffu, v, 8);
        v += __shfl_down_sync(0xffffffffu, v, 4);
        v += __shfl_down_sync(0xffffffffu, v, 2);
        v += __shfl_down_sync(0xffffffffu, v, 1);
        if (lane == 0) __stcg(&g_part[1][warp][bid], v);
    }

    unsigned phase = 1;
    gsync(phase * 4);

    // ---- 22 fused steps ----
    int cand_base = 0, ncand = 4;
    for (int s = 1; s <= 22; s++) {
        const int parity = s & 1, pr = s & 1, pw = (s + 1) & 1;

        // prologue: reduce decode partials (warp per class), argmax
        if (warp < ncand) {
            const float* p = g_part[pr][warp];
            float a = __ldcg(&p[lane]) + __ldcg(&p[lane + 32])
                    + __ldcg(&p[lane + 64]) + __ldcg(&p[lane + 96]);
            a += __shfl_down_sync(0xffffffffu, a, 16);
            a += __shfl_down_sync(0xffffffffu, a, 8);
            a += __shfl_down_sync(0xffffffffu, a, 4);
            a += __shfl_down_sync(0xffffffffu, a, 2);
            a += __shfl_down_sync(0xffffffffu, a, 1);
            if (lane == 0) slog[warp] = a;
        }
        __syncthreads();
        if (t == 0) {
            int best = 0; float bv = slog[0];
            for (int cc = 1; cc < ncand; cc++)
                if (slog[cc] > bv) { bv = slog[cc]; best = cc; }
            ssel = cand_base + best;
        }
        __syncthreads();

        // prefetch the selected precomputed gate row into smem (overlaps GEMV)
        if (t < 256) {
            int q = t >> 6, rest = t & 63;       // rest = g*16 + u
            spre[t] = __ldg(&g_pre[q][ssel][(rest >> 4) * H + j0 + (rest & 15)]);
        }

        // main GEMV: 16 rows (gate rg) x H, k-prefix from smem
        const float4* h4 = (const float4*)g_h[parity ^ 1];
        float acc[16];
#pragma unroll
        for (int i = 0; i < 16; i++) acc[i] = 0.0f;

        {
            // iteration A: k4 = kq (warps 0-5 of each gate: smem; 6-7: global)
            float4 hv = __ldcg(&h4[kq]);
            if (wig < 6) {
#pragma unroll
                for (int rl = 0; rl < 16; rl++) {
                    float4 w = wc4[(rg * 16 + rl) * KC4 + kq];
                    acc[rl] += hv.x * w.x + hv.y * w.y + hv.z * w.z + hv.w * w.w;
                }
            } else {
#pragma unroll
                for (int rl = 0; rl < 16; rl++) {
                    float4 w = __ldcg(&W4[(size_t)(rg * H + j0 + rl) * (H / 4) + kq]);
                    acc[rl] += hv.x * w.x + hv.y * w.y + hv.z * w.z + hv.w * w.w;
                }
            }
            // iteration B: k4 = kq + 256 (all global)
            int k4 = kq + 256;
            float4 hv2 = __ldcg(&h4[k4]);
#pragma unroll
            for (int rl = 0; rl < 16; rl++) {
                float4 w = __ldcg(&W4[(size_t)(rg * H + j0 + rl) * (H / 4) + k4]);
                acc[rl] += hv2.x * w.x + hv2.y * w.y + hv2.z * w.z + hv2.w * w.w;
            }
        }

#pragma unroll
        for (int i = 0; i < 16; i++) {
            float a = acc[i];
            a += __shfl_down_sync(0xffffffffu, a, 16);
            a += __shfl_down_sync(0xffffffffu, a, 8);
            a += __shfl_down_sync(0xffffffffu, a, 4);
            a += __shfl_down_sync(0xffffffffu, a, 2);
            a += __shfl_down_sync(0xffffffffu, a, 1);
            if (lane == 0) wsum[rg][wig][i] = a;
        }
        __syncthreads();
        if (t < 64) {
            float sm = 0.0f;
#pragma unroll
            for (int w = 0; w < 8; w++) sm += wsum[t >> 4][w][t & 15];
            sg[t] = sm;
        }
        __syncthreads();

        if (t < 16) {
            int j = j0 + t;
            float gi = sg[     t] + spre[     t] + spre[64 +      t] + spre[128 +      t] + spre[192 +      t];
            float gf = sg[16 + t] + spre[16 + t] + spre[64 + 16 + t] + spre[128 + 16 + t] + spre[192 + 16 + t];
            float gg = sg[32 + t] + spre[32 + t] + spre[64 + 32 + t] + spre[128 + 32 + t] + spre[192 + 32 + t];
            float go = sg[48 + t] + spre[48 + t] + spre[64 + 48 + t] + spre[128 + 48 + t] + spre[192 + 48 + t];
            float c2 = sigmoidf_(gf) * scell[t] + sigmoidf_(gi) * tanhf(gg);
            float h2 = sigmoidf_(go) * tanhf(c2);
            scell[t] = c2;
            sunit[t] = h2;
            __stcg(&g_h[parity][j], h2);
            if (s == 22) __stcg(&g_c[j], c2);
        }
        __syncthreads();

        // epilogue: this step's decode partials (warp per class)
        const float* dec;
        int ncls;
        if (s & 1) {
            int bq = (s + 1) / 2;
            dec  = dec_block + (size_t)(bq - 1) * (NB - 1) * H;
            ncls = bq;
        } else {
            dec  = dec_act + (size_t)(s / 2) * 4 * H;
            ncls = 4;
        }
        if (warp < ncls) {
            float v = (lane < 16) ? sunit[lane] * __ldg(&dec[(size_t)warp * H + j0 + lane]) : 0.0f;
            v += __shfl_down_sync(0xffffffffu, v, 8);
            v += __shfl_down_sync(0xffffffffu, v, 4);
            v += __shfl_down_sync(0xffffffffu, v, 2);
            v += __shfl_down_sync(0xffffffffu, v, 1);
            if (lane == 0) __stcg(&g_part[pw][warp][bid], v);
        }

        cand_base += ncand;
        ncand = ((s + 1) & 1) ? 4 : ((s + 1) >> 1);

        ++phase;
        gsync(phase * 4);
    }

    // ---- final argmax (4 classes, partials in g_part[1]) ----
    if (warp < 4) {
        const float* p = g_part[1][warp];
        float a = __ldcg(&p[lane]) + __ldcg(&p[lane + 32])
                + __ldcg(&p[lane + 64]) + __ldcg(&p[lane + 96]);
        a += __shfl_down_sync(0xffffffffu, a, 16);
        a += __shfl_down_sync(0xffffffffu, a, 8);
        a += __shfl_down_sync(0xffffffffu, a, 4);
        a += __shfl_down_sync(0xffffffffu, a, 2);
        a += __shfl_down_sync(0xffffffffu, a, 1);
        if (lane == 0) slog[warp] = a;
    }
    __syncthreads();
    if (t == 0) {
        int best = 0; float bv = slog[0];
        for (int cc = 1; cc < 4; cc++)
            if (slog[cc] > bv) { bv = slog[cc]; best = cc; }
        ssel = best;
    }
    __syncthreads();

    // ---- output broadcast ----
    const float fidx = (float)ssel;
    const long HB = (long)B * H;
    for (long i = (long)bid * 1024 + t; i < out_size; i += (long)NBLK * 1024) {
        float v;
        if (i < B)               v = fidx;
        else if (i < B + HB)     v = __ldcg(&g_h[0][(i - B) & (H - 1)]);
        else if (i < B + 2 * HB) v = __ldcg(&g_c[(i - B - HB) & (H - 1)]);
        else                     v = 0.0f;
        __stcs(out + i, v);
    }
}

// ---------------------------------------------------------------------------
extern "C" void kernel_launch(void* const* d_in, const int* in_sizes, int n_in,
                              void* d_out, int out_size) {
    (void)in_sizes; (void)n_in;
    const float* Wih       = (const float*)d_in[1];
    const float* Whh       = (const float*)d_in[2];
    const float* b_ih      = (const float*)d_in[3];
    const float* b_hh      = (const float*)d_in[4];
    const float* enc_act   = (const float*)d_in[5];
    const float* enc_block = (const float*)d_in[6];
    const float* dec_act   = (const float*)d_in[7];
    const float* dec_block = (const float*)d_in[8];

    static int attr_done = 0;
    if (!attr_done) {
        cudaFuncSetAttribute(k_persist, cudaFuncAttributeMaxDynamicSharedMemorySize, P_DSMEM);
        cudaFuncSetAttribute(k_pre, cudaFuncAttributeMaxDynamicSharedMemorySize, PRE_DSMEM);
        attr_done = 1;
    }

    k_init<<<1, 256>>>();
    k_gather<<<NROW, 256>>>(enc_act, enc_block);
    k_pre<<<128, 256, PRE_DSMEM>>>(Wih, b_ih, b_hh);
    k_persist<<<NBLK, 1024, P_DSMEM>>>(Whh, b_ih, b_hh, dec_act, dec_block,
                                       (float*)d_out, out_size);
}